// round 15
// baseline (speedup 1.0000x reference)
#include <cuda_runtime.h>

#define NMAX 50000
#define EMAX 800000
#define DD 64
#define NPB 64            // dst nodes per block
#define AP 64             // sA pitch (row-major [node][k])
#define WP 68             // sW pitch (transposed [k][j])
#define SCAN_CHUNK 1024
#define MAXB ((NMAX + SCAN_CHUNK - 1) / SCAN_CHUNK)   // 49
#define DSTMASK 0x1FFFF   // low 17 bits = dst id (n < 131072)

// -------- device scratch (no allocations allowed) --------
// g_deg is zero at module load and restored to zero by scan_kernel every
// invocation -> self-restoring invariant, no init kernel needed.
__device__ int   g_src[EMAX];
__device__ int   g_dst[EMAX];      // packed: (rank << 17) | dst
__device__ int   g_deg[NMAX];
__device__ int   g_rowptr[NMAX + 2];
__device__ int   g_col[EMAX];
__device__ int   g_bsum[MAXB + 1];
__device__ float g_h1[(size_t)NMAX * DD];

// ---- packed f32x2 helpers (sm_103a; ptxas never auto-emits FFMA2) ----
__device__ __forceinline__ unsigned long long bcast2(float a) {
    unsigned long long r;
    asm("mov.b64 %0, {%1, %1};" : "=l"(r) : "f"(a));
    return r;
}
__device__ __forceinline__ void fma2(unsigned long long& acc,
                                     unsigned long long a, unsigned long long b) {
    asm("fma.rn.f32x2 %0, %1, %2, %0;" : "+l"(acc) : "l"(a), "l"(b));
}
__device__ __forceinline__ void add2(unsigned long long& acc, unsigned long long b) {
    asm("add.rn.f32x2 %0, %0, %1;" : "+l"(acc) : "l"(b));
}
__device__ __forceinline__ void unpack2(unsigned long long p, float& lo, float& hi) {
    asm("mov.b64 {%0, %1}, %2;" : "=f"(lo), "=f"(hi) : "l"(p));
}

// ============ convert + count + inline dtype detection ============
__global__ void convert_count_kernel(const void* __restrict__ edge, int e, int n) {
    int t = threadIdx.x;
    int i = blockIdx.x * blockDim.x + t;
    const long long* p64 = (const long long*)edge;
    long long probe = 0;
    if (t < 64) probe = p64[t];
    int is64 = __syncthreads_and(t >= 64 || (probe >= 0 && probe < n));

    if (i >= e) return;
    int s, d;
    if (is64) {
        s = (int)p64[i];
        d = (int)p64[e + i];
    } else {
        const int* p = (const int*)edge;
        s = p[i];
        d = p[e + i];
    }
    s = min(max(s, 0), n - 1);
    d = min(max(d, 0), n - 1);
    g_src[i] = s;
    int r = atomicAdd(&g_deg[d], 1);
    g_dst[i] = d | (r << 17);
}

// ============ coalesced scan: bsum -> scan (block offsets inlined) ============
__global__ void bsum_kernel(int n) {
    __shared__ int ws[32];
    int b = blockIdx.x, t = threadIdx.x;
    int lane = t & 31, wid = t >> 5;
    int i = b * SCAN_CHUNK + t;
    int v = (i < n) ? g_deg[i] : 0;
    #pragma unroll
    for (int o = 16; o > 0; o >>= 1) v += __shfl_xor_sync(0xffffffffu, v, o);
    if (lane == 0) ws[wid] = v;
    __syncthreads();
    if (t < 32) {
        int s = ws[t];
        #pragma unroll
        for (int o = 16; o > 0; o >>= 1) s += __shfl_xor_sync(0xffffffffu, s, o);
        if (t == 0) g_bsum[b] = s;
    }
}

// per-chunk exclusive scan; block offset computed in-kernel from g_bsum.
// Also restores g_deg[i] = 0 after consumption (invariant for next replay).
__global__ void scan_kernel(int n, int e) {
    __shared__ int ws[32];
    __shared__ int sOff;
    int b = blockIdx.x, t = threadIdx.x;
    int lane = t & 31, wid = t >> 5;

    if (wid == 0) {
        int off = 0;
        for (int j = lane; j < b; j += 32) off += g_bsum[j];
        #pragma unroll
        for (int o = 16; o > 0; o >>= 1) off += __shfl_xor_sync(0xffffffffu, off, o);
        if (lane == 0) sOff = off;
    }

    int i = b * SCAN_CHUNK + t;
    int v = (i < n) ? g_deg[i] : 0;
    int x = v;
    #pragma unroll
    for (int o = 1; o < 32; o <<= 1) {
        int y = __shfl_up_sync(0xffffffffu, x, o);
        if (lane >= o) x += y;
    }
    if (lane == 31) ws[wid] = x;
    __syncthreads();
    if (wid == 0) {
        int w = ws[lane];
        #pragma unroll
        for (int o = 1; o < 32; o <<= 1) {
            int y = __shfl_up_sync(0xffffffffu, w, o);
            if (lane >= o) w += y;
        }
        ws[lane] = w;
    }
    __syncthreads();
    int incl = x + (wid > 0 ? ws[wid - 1] : 0);
    int excl = incl - v + sOff;
    if (i < n) {
        g_rowptr[i] = excl;
        g_deg[i] = 0;            // restore invariant for next invocation
    }
    if (b == 0 && t == 0) g_rowptr[n] = e;
}

// atomic-free fill: slot = rowptr[dst] + rank (rank packed in g_dst)
__global__ void fill_kernel(int e) {
    int i = blockIdx.x * blockDim.x + threadIdx.x;
    if (i < e) {
        int v = g_dst[i];
        int d = v & DSTMASK;
        int r = v >> 17;
        g_col[g_rowptr[d] + r] = g_src[i];
    }
}

// ================= fused layer =================
// mode 0: in = x param, out = g_h1, epilogue leaky_relu(0.01)
// mode 1: in = g_h1,    out = out param, epilogue row-L2-normalize
__global__ __launch_bounds__(256) void layer_kernel(
    const float* __restrict__ in_p,
    const float* __restrict__ Wl,      // [64,64] row-major
    const float* __restrict__ bias,    // [64]
    const float* __restrict__ Wr,      // [64,64] row-major
    float* __restrict__ out_p,
    int n, int mode)
{
    __shared__ float sA[NPB * AP];     // [64 nodes][64 k] row-major
    __shared__ float sW[64 * WP];      // [64 k][64 j] transposed weight
    __shared__ float sB[64];

    const float* __restrict__ in = (mode == 0) ? in_p : g_h1;
    float* __restrict__ out      = (mode == 0) ? g_h1 : out_p;

    const unsigned full = 0xffffffffu;
    int t = threadIdx.x;
    int wid = t >> 5, lane = t & 31;
    int half = lane >> 4;        // 0/1: which edge of the pair
    int c4 = (lane & 15) * 4;    // float4 column group
    int node0 = blockIdx.x * NPB;

    // load Wl^T and bias
    for (int idx = t; idx < 64 * 64; idx += 256) {
        int j = idx >> 6, k = idx & 63;
        sW[k * WP + j] = Wl[idx];
    }
    if (t < 64) sB[t] = bias[t];

    // ---- prefetch rowptr for this warp's 8 nodes (lanes 0..15) ----
    int pidx;
    if (lane < 8)       pidx = node0 + wid + lane * 8;
    else if (lane < 16) pidx = node0 + wid + (lane - 8) * 8 + 1;
    else                pidx = n;
    pidx = min(pidx, n);
    int rp = g_rowptr[pidx];

    // ---- phase 1: mean aggregation -> sA ----
    // 8-edge unroll: 4 index LDGs issued together, then 4 independent
    // feature LDG.128s in flight (MLP 4 within iteration).
    #pragma unroll
    for (int it = 0; it < 8; it++) {
        int ni = wid + it * 8;
        int node = node0 + ni;
        float4 a0 = {0.f, 0.f, 0.f, 0.f}, a1 = {0.f, 0.f, 0.f, 0.f};
        float4 a2 = {0.f, 0.f, 0.f, 0.f}, a3 = {0.f, 0.f, 0.f, 0.f};
        int beg = __shfl_sync(full, rp, it);
        int end = __shfl_sync(full, rp, it + 8);
        if (node < n) {
            int e0 = beg;
            for (; e0 + 8 <= end; e0 += 8) {
                int s0 = g_col[e0 + half];
                int s1 = g_col[e0 + 2 + half];
                int s2 = g_col[e0 + 4 + half];
                int s3 = g_col[e0 + 6 + half];
                float4 v0 = *(const float4*)&in[(size_t)s0 * 64 + c4];
                float4 v1 = *(const float4*)&in[(size_t)s1 * 64 + c4];
                float4 v2 = *(const float4*)&in[(size_t)s2 * 64 + c4];
                float4 v3 = *(const float4*)&in[(size_t)s3 * 64 + c4];
                a0.x += v0.x; a0.y += v0.y; a0.z += v0.z; a0.w += v0.w;
                a1.x += v1.x; a1.y += v1.y; a1.z += v1.z; a1.w += v1.w;
                a2.x += v2.x; a2.y += v2.y; a2.z += v2.z; a2.w += v2.w;
                a3.x += v3.x; a3.y += v3.y; a3.z += v3.z; a3.w += v3.w;
            }
            if (e0 + 4 <= end) {
                int s0 = g_col[e0 + half];
                int s1 = g_col[e0 + 2 + half];
                float4 v0 = *(const float4*)&in[(size_t)s0 * 64 + c4];
                float4 v1 = *(const float4*)&in[(size_t)s1 * 64 + c4];
                a0.x += v0.x; a0.y += v0.y; a0.z += v0.z; a0.w += v0.w;
                a1.x += v1.x; a1.y += v1.y; a1.z += v1.z; a1.w += v1.w;
                e0 += 4;
            }
            if (e0 + 2 <= end) {
                int s0 = g_col[e0 + half];
                float4 v0 = *(const float4*)&in[(size_t)s0 * 64 + c4];
                a0.x += v0.x; a0.y += v0.y; a0.z += v0.z; a0.w += v0.w;
                e0 += 2;
            }
            if (e0 < end && half == 0) {
                int s0 = g_col[e0];
                float4 v0 = *(const float4*)&in[(size_t)s0 * 64 + c4];
                a1.x += v0.x; a1.y += v0.y; a1.z += v0.z; a1.w += v0.w;
            }
            a0.x += a1.x + a2.x + a3.x;
            a0.y += a1.y + a2.y + a3.y;
            a0.z += a1.z + a2.z + a3.z;
            a0.w += a1.w + a2.w + a3.w;
            a0.x += __shfl_xor_sync(full, a0.x, 16);
            a0.y += __shfl_xor_sync(full, a0.y, 16);
            a0.z += __shfl_xor_sync(full, a0.z, 16);
            a0.w += __shfl_xor_sync(full, a0.w, 16);
            int deg = end - beg;
            float inv = 1.0f / (float)(deg > 0 ? deg : 1);
            a0.x *= inv; a0.y *= inv; a0.z *= inv; a0.w *= inv;
        }
        if (half == 0)
            *(float4*)&sA[ni * AP + c4] = a0;
    }
    __syncthreads();

    // ---- GEMM with packed f32x2 accumulators (4x4 tile) ----
    int rg = t >> 4, cg = t & 15;
    int i0 = rg * 4, j0 = cg * 4;
    unsigned long long accp[4][2] = {};

    // pass 1: acc += mean @ Wl^T
    #pragma unroll 4
    for (int k = 0; k < 64; k += 4) {
        float4 a0 = *(const float4*)&sA[(i0 + 0) * AP + k];
        float4 a1 = *(const float4*)&sA[(i0 + 1) * AP + k];
        float4 a2 = *(const float4*)&sA[(i0 + 2) * AP + k];
        float4 a3 = *(const float4*)&sA[(i0 + 3) * AP + k];
        #pragma unroll
        for (int kk = 0; kk < 4; kk++) {
            ulonglong2 wp = *(const ulonglong2*)&sW[(k + kk) * WP + j0];
            float s0 = (kk == 0) ? a0.x : (kk == 1) ? a0.y : (kk == 2) ? a0.z : a0.w;
            float s1 = (kk == 0) ? a1.x : (kk == 1) ? a1.y : (kk == 2) ? a1.z : a1.w;
            float s2 = (kk == 0) ? a2.x : (kk == 1) ? a2.y : (kk == 2) ? a2.z : a2.w;
            float s3 = (kk == 0) ? a3.x : (kk == 1) ? a3.y : (kk == 2) ? a3.z : a3.w;
            unsigned long long p;
            p = bcast2(s0); fma2(accp[0][0], p, wp.x); fma2(accp[0][1], p, wp.y);
            p = bcast2(s1); fma2(accp[1][0], p, wp.x); fma2(accp[1][1], p, wp.y);
            p = bcast2(s2); fma2(accp[2][0], p, wp.x); fma2(accp[2][1], p, wp.y);
            p = bcast2(s3); fma2(accp[3][0], p, wp.x); fma2(accp[3][1], p, wp.y);
        }
    }
    __syncthreads();

    // swap operands: sA <- x (reload from global, coalesced), sW <- Wr^T
    for (int i = t; i < NPB * 16; i += 256) {     // 16 float4 per row
        int nd = i >> 4;
        int col4 = (i & 15) * 4;
        int node = node0 + nd;
        float4 v = {0.f, 0.f, 0.f, 0.f};
        if (node < n)
            v = *(const float4*)&in[(size_t)node * 64 + col4];
        *(float4*)&sA[nd * AP + col4] = v;
    }
    for (int idx = t; idx < 64 * 64; idx += 256) {
        int j = idx >> 6, k = idx & 63;
        sW[k * WP + j] = Wr[idx];
    }
    __syncthreads();

    // pass 2: acc += x @ Wr^T
    #pragma unroll 4
    for (int k = 0; k < 64; k += 4) {
        float4 a0 = *(const float4*)&sA[(i0 + 0) * AP + k];
        float4 a1 = *(const float4*)&sA[(i0 + 1) * AP + k];
        float4 a2 = *(const float4*)&sA[(i0 + 2) * AP + k];
        float4 a3 = *(const float4*)&sA[(i0 + 3) * AP + k];
        #pragma unroll
        for (int kk = 0; kk < 4; kk++) {
            ulonglong2 wp = *(const ulonglong2*)&sW[(k + kk) * WP + j0];
            float s0 = (kk == 0) ? a0.x : (kk == 1) ? a0.y : (kk == 2) ? a0.z : a0.w;
            float s1 = (kk == 0) ? a1.x : (kk == 1) ? a1.y : (kk == 2) ? a1.z : a1.w;
            float s2 = (kk == 0) ? a2.x : (kk == 1) ? a2.y : (kk == 2) ? a2.z : a2.w;
            float s3 = (kk == 0) ? a3.x : (kk == 1) ? a3.y : (kk == 2) ? a3.z : a3.w;
            unsigned long long p;
            p = bcast2(s0); fma2(accp[0][0], p, wp.x); fma2(accp[0][1], p, wp.y);
            p = bcast2(s1); fma2(accp[1][0], p, wp.x); fma2(accp[1][1], p, wp.y);
            p = bcast2(s2); fma2(accp[2][0], p, wp.x); fma2(accp[2][1], p, wp.y);
            p = bcast2(s3); fma2(accp[3][0], p, wp.x); fma2(accp[3][1], p, wp.y);
        }
    }

    // bias (packed) + unpack
    ulonglong2 bp = *(const ulonglong2*)&sB[j0];
    float acc[4][4];
    #pragma unroll
    for (int r = 0; r < 4; r++) {
        add2(accp[r][0], bp.x);
        add2(accp[r][1], bp.y);
        unpack2(accp[r][0], acc[r][0], acc[r][1]);
        unpack2(accp[r][1], acc[r][2], acc[r][3]);
    }

    if (mode == 0) {
        #pragma unroll
        for (int r = 0; r < 4; r++) {
            int node = node0 + i0 + r;
            if (node < n) {
                float4 st; float v;
                v = acc[r][0]; st.x = (v >= 0.f) ? v : 0.01f * v;
                v = acc[r][1]; st.y = (v >= 0.f) ? v : 0.01f * v;
                v = acc[r][2]; st.z = (v >= 0.f) ? v : 0.01f * v;
                v = acc[r][3]; st.w = (v >= 0.f) ? v : 0.01f * v;
                *(float4*)&out[(size_t)node * 64 + j0] = st;
            }
        }
    } else {
        // stage into sA, per-row L2 normalize
        __syncthreads();
        #pragma unroll
        for (int r = 0; r < 4; r++)
            *(float4*)&sA[(i0 + r) * AP + j0] =
                make_float4(acc[r][0], acc[r][1], acc[r][2], acc[r][3]);
        __syncthreads();
        #pragma unroll
        for (int it = 0; it < 8; it++) {
            int ni = wid + it * 8;
            int node = node0 + ni;
            if (node >= n) continue;
            float2 v = *(const float2*)&sA[ni * AP + 2 * lane];
            float ss = v.x * v.x + v.y * v.y;
            #pragma unroll
            for (int o = 16; o > 0; o >>= 1)
                ss += __shfl_xor_sync(full, ss, o);
            float s = 1.0f / fmaxf(sqrtf(ss), 1e-12f);
            *(float2*)&out[(size_t)node * 64 + 2 * lane] =
                make_float2(v.x * s, v.y * s);
        }
    }
}

// ================= launch (kernels ONLY — no host API calls) =================
extern "C" void kernel_launch(void* const* d_in, const int* in_sizes, int n_in,
                              void* d_out, int out_size)
{
    const float* x    = (const float*)d_in[0];
    const void*  edge = (const void*)d_in[1];
    // d_in[2] = edge_weight (ignored by SAGEConv)
    const float* W1l = (const float*)d_in[3];
    const float* b1  = (const float*)d_in[4];
    const float* W1r = (const float*)d_in[5];
    const float* W2l = (const float*)d_in[6];
    const float* b2  = (const float*)d_in[7];
    const float* W2r = (const float*)d_in[8];
    float* out = (float*)d_out;

    int n = in_sizes[0] / DD;
    int e = in_sizes[1] / 2;
    int nb = (n + SCAN_CHUNK - 1) / SCAN_CHUNK;

    convert_count_kernel<<<(e + 255) / 256, 256>>>(edge, e, n);
    bsum_kernel<<<nb, SCAN_CHUNK>>>(n);
    scan_kernel<<<nb, SCAN_CHUNK>>>(n, e);
    fill_kernel<<<(e + 255) / 256, 256>>>(e);

    int nblocks = (n + NPB - 1) / NPB;
    layer_kernel<<<nblocks, 256>>>(x, W1l, b1, W1r, nullptr, n, 0); // -> g_h1
    layer_kernel<<<nblocks, 256>>>(x, W2l, b2, W2r, out,     n, 1); // g_h1 -> out
}

// round 16
// speedup vs baseline: 1.0165x; 1.0165x over previous
#include <cuda_runtime.h>

#define NMAX 50000
#define EMAX 800000
#define DD 64
#define NPB 64            // dst nodes per block
#define AP 64             // sA pitch (row-major [node][k])
#define WP 68             // sW pitch (transposed [k][j])
#define SCAN_CHUNK 256
#define MAXB ((NMAX + SCAN_CHUNK - 1) / SCAN_CHUNK)   // 196
#define BPAD 32           // 128B padding: one LTS line per chunk counter
#define DSTMASK 0x1FFFF   // low 17 bits = dst id (n < 131072)

// -------- device scratch (no allocations allowed) --------
// g_deg and g_bsum are zero at module load and restored to zero by
// scan_kernel / fill_kernel every invocation -> self-restoring invariants.
__device__ int   g_src[EMAX];
__device__ int   g_dst[EMAX];      // packed: (rank << 17) | dst
__device__ int   g_deg[NMAX];
__device__ int   g_rowptr[NMAX + 2];
__device__ int   g_col[EMAX];
__device__ int   g_bsum[MAXB * BPAD];   // per-256-chunk edge counts, padded
__device__ float g_h1[(size_t)NMAX * DD];

// ---- packed f32x2 helpers (sm_103a; ptxas never auto-emits FFMA2) ----
__device__ __forceinline__ unsigned long long bcast2(float a) {
    unsigned long long r;
    asm("mov.b64 %0, {%1, %1};" : "=l"(r) : "f"(a));
    return r;
}
__device__ __forceinline__ void fma2(unsigned long long& acc,
                                     unsigned long long a, unsigned long long b) {
    asm("fma.rn.f32x2 %0, %1, %2, %0;" : "+l"(acc) : "l"(a), "l"(b));
}
__device__ __forceinline__ void add2(unsigned long long& acc, unsigned long long b) {
    asm("add.rn.f32x2 %0, %0, %1;" : "+l"(acc) : "l"(b));
}
__device__ __forceinline__ void unpack2(unsigned long long p, float& lo, float& hi) {
    asm("mov.b64 {%0, %1}, %2;" : "=f"(lo), "=f"(hi) : "l"(p));
}

// ============ convert + count (deg AND per-chunk) + inline dtype detect ============
__global__ void convert_count_kernel(const void* __restrict__ edge, int e, int n) {
    int t = threadIdx.x;
    int i = blockIdx.x * blockDim.x + t;
    const long long* p64 = (const long long*)edge;
    long long probe = 0;
    if (t < 64) probe = p64[t];
    int is64 = __syncthreads_and(t >= 64 || (probe >= 0 && probe < n));

    if (i >= e) return;
    int s, d;
    if (is64) {
        s = (int)p64[i];
        d = (int)p64[e + i];
    } else {
        const int* p = (const int*)edge;
        s = p[i];
        d = p[e + i];
    }
    s = min(max(s, 0), n - 1);
    d = min(max(d, 0), n - 1);
    g_src[i] = s;
    int r = atomicAdd(&g_deg[d], 1);        // rank within node
    g_dst[i] = d | (r << 17);
    atomicAdd(&g_bsum[(d >> 8) * BPAD], 1); // chunk count (RED, no return)
}

// per-chunk exclusive scan; block offset from padded chunk counters.
// Restores g_deg[i] = 0 after consumption (invariant for next replay).
__global__ __launch_bounds__(SCAN_CHUNK) void scan_kernel(int n, int e) {
    __shared__ int ws[32];
    __shared__ int sOff;
    int b = blockIdx.x, t = threadIdx.x;
    int lane = t & 31, wid = t >> 5;

    if (wid == 0) {
        int off = 0;
        for (int j = lane; j < b; j += 32) off += g_bsum[j * BPAD];
        #pragma unroll
        for (int o = 16; o > 0; o >>= 1) off += __shfl_xor_sync(0xffffffffu, off, o);
        if (lane == 0) sOff = off;
    }

    int i = b * SCAN_CHUNK + t;
    int v = (i < n) ? g_deg[i] : 0;
    int x = v;
    #pragma unroll
    for (int o = 1; o < 32; o <<= 1) {
        int y = __shfl_up_sync(0xffffffffu, x, o);
        if (lane >= o) x += y;
    }
    if (lane == 31) ws[wid] = x;
    __syncthreads();
    if (wid == 0) {
        int w = (lane < (SCAN_CHUNK / 32)) ? ws[lane] : 0;
        #pragma unroll
        for (int o = 1; o < 32; o <<= 1) {
            int y = __shfl_up_sync(0xffffffffu, w, o);
            if (lane >= o) w += y;
        }
        ws[lane] = w;
    }
    __syncthreads();
    int incl = x + (wid > 0 ? ws[wid - 1] : 0);
    int excl = incl - v + sOff;
    if (i < n) {
        g_rowptr[i] = excl;
        g_deg[i] = 0;            // restore invariant for next invocation
    }
    if (b == 0 && t == 0) g_rowptr[n] = e;
}

// atomic-free fill: slot = rowptr[dst] + rank (rank packed in g_dst).
// Also restores the chunk counters to zero (invariant for next replay).
__global__ void fill_kernel(int e) {
    int i = blockIdx.x * blockDim.x + threadIdx.x;
    if (i < MAXB) g_bsum[i * BPAD] = 0;
    if (i < e) {
        int v = g_dst[i];
        int d = v & DSTMASK;
        int r = v >> 17;
        g_col[g_rowptr[d] + r] = g_src[i];
    }
}

// ================= fused layer (127.5us winner, frozen) =================
// mode 0: in = x param, out = g_h1, epilogue leaky_relu(0.01)
// mode 1: in = g_h1,    out = out param, epilogue row-L2-normalize
__global__ __launch_bounds__(256) void layer_kernel(
    const float* __restrict__ in_p,
    const float* __restrict__ Wl,      // [64,64] row-major
    const float* __restrict__ bias,    // [64]
    const float* __restrict__ Wr,      // [64,64] row-major
    float* __restrict__ out_p,
    int n, int mode)
{
    __shared__ float sA[NPB * AP];     // [64 nodes][64 k] row-major
    __shared__ float sW[64 * WP];      // [64 k][64 j] transposed weight
    __shared__ float sB[64];

    const float* __restrict__ in = (mode == 0) ? in_p : g_h1;
    float* __restrict__ out      = (mode == 0) ? g_h1 : out_p;

    const unsigned full = 0xffffffffu;
    int t = threadIdx.x;
    int wid = t >> 5, lane = t & 31;
    int half = lane >> 4;        // 0/1: which edge of the pair
    int c4 = (lane & 15) * 4;    // float4 column group
    int node0 = blockIdx.x * NPB;

    // load Wl^T and bias
    for (int idx = t; idx < 64 * 64; idx += 256) {
        int j = idx >> 6, k = idx & 63;
        sW[k * WP + j] = Wl[idx];
    }
    if (t < 64) sB[t] = bias[t];

    // ---- prefetch rowptr for this warp's 8 nodes (lanes 0..15) ----
    int pidx;
    if (lane < 8)       pidx = node0 + wid + lane * 8;
    else if (lane < 16) pidx = node0 + wid + (lane - 8) * 8 + 1;
    else                pidx = n;
    pidx = min(pidx, n);
    int rp = g_rowptr[pidx];

    // ---- prefetch self rows x[node] for all 8 nodes ----
    float2 xs[8];
    #pragma unroll
    for (int it = 0; it < 8; it++) {
        int node = min(node0 + wid + it * 8, n - 1);
        xs[it] = *(const float2*)&in[(size_t)node * 64 + 2 * lane];
    }

    // ---- phase 1: mean aggregation -> sA ----
    #pragma unroll
    for (int it = 0; it < 8; it++) {
        int ni = wid + it * 8;
        int node = node0 + ni;
        float4 a0 = {0.f, 0.f, 0.f, 0.f}, a1 = {0.f, 0.f, 0.f, 0.f};
        int beg = __shfl_sync(full, rp, it);
        int end = __shfl_sync(full, rp, it + 8);
        if (node < n) {
            int e0 = beg;
            for (; e0 + 4 <= end; e0 += 4) {
                int sa = g_col[e0 + half];
                int sb = g_col[e0 + 2 + half];
                float4 v0 = *(const float4*)&in[(size_t)sa * 64 + c4];
                float4 v1 = *(const float4*)&in[(size_t)sb * 64 + c4];
                a0.x += v0.x; a0.y += v0.y; a0.z += v0.z; a0.w += v0.w;
                a1.x += v1.x; a1.y += v1.y; a1.z += v1.z; a1.w += v1.w;
            }
            if (e0 + 2 <= end) {
                int sa = g_col[e0 + half];
                float4 v0 = *(const float4*)&in[(size_t)sa * 64 + c4];
                a0.x += v0.x; a0.y += v0.y; a0.z += v0.z; a0.w += v0.w;
                e0 += 2;
            }
            if (e0 < end && half == 0) {
                int sa = g_col[e0];
                float4 v0 = *(const float4*)&in[(size_t)sa * 64 + c4];
                a1.x += v0.x; a1.y += v0.y; a1.z += v0.z; a1.w += v0.w;
            }
            a0.x += a1.x; a0.y += a1.y; a0.z += a1.z; a0.w += a1.w;
            a0.x += __shfl_xor_sync(full, a0.x, 16);
            a0.y += __shfl_xor_sync(full, a0.y, 16);
            a0.z += __shfl_xor_sync(full, a0.z, 16);
            a0.w += __shfl_xor_sync(full, a0.w, 16);
            int deg = end - beg;
            float inv = 1.0f / (float)(deg > 0 ? deg : 1);
            a0.x *= inv; a0.y *= inv; a0.z *= inv; a0.w *= inv;
        }
        if (half == 0)
            *(float4*)&sA[ni * AP + c4] = a0;
    }
    __syncthreads();

    // ---- GEMM with packed f32x2 accumulators (4x4 tile) ----
    int rg = t >> 4, cg = t & 15;
    int i0 = rg * 4, j0 = cg * 4;
    unsigned long long accp[4][2] = {};

    // pass 1: acc += mean @ Wl^T
    #pragma unroll 4
    for (int k = 0; k < 64; k += 4) {
        float4 a0 = *(const float4*)&sA[(i0 + 0) * AP + k];
        float4 a1 = *(const float4*)&sA[(i0 + 1) * AP + k];
        float4 a2 = *(const float4*)&sA[(i0 + 2) * AP + k];
        float4 a3 = *(const float4*)&sA[(i0 + 3) * AP + k];
        #pragma unroll
        for (int kk = 0; kk < 4; kk++) {
            ulonglong2 wp = *(const ulonglong2*)&sW[(k + kk) * WP + j0];
            float s0 = (kk == 0) ? a0.x : (kk == 1) ? a0.y : (kk == 2) ? a0.z : a0.w;
            float s1 = (kk == 0) ? a1.x : (kk == 1) ? a1.y : (kk == 2) ? a1.z : a1.w;
            float s2 = (kk == 0) ? a2.x : (kk == 1) ? a2.y : (kk == 2) ? a2.z : a2.w;
            float s3 = (kk == 0) ? a3.x : (kk == 1) ? a3.y : (kk == 2) ? a3.z : a3.w;
            unsigned long long p;
            p = bcast2(s0); fma2(accp[0][0], p, wp.x); fma2(accp[0][1], p, wp.y);
            p = bcast2(s1); fma2(accp[1][0], p, wp.x); fma2(accp[1][1], p, wp.y);
            p = bcast2(s2); fma2(accp[2][0], p, wp.x); fma2(accp[2][1], p, wp.y);
            p = bcast2(s3); fma2(accp[3][0], p, wp.x); fma2(accp[3][1], p, wp.y);
        }
    }
    __syncthreads();

    // swap operands: sA <- x, sW <- Wr^T
    #pragma unroll
    for (int it = 0; it < 8; it++) {
        int ni = wid + it * 8;
        *(float2*)&sA[ni * AP + 2 * lane] = xs[it];
    }
    for (int idx = t; idx < 64 * 64; idx += 256) {
        int j = idx >> 6, k = idx & 63;
        sW[k * WP + j] = Wr[idx];
    }
    __syncthreads();

    // pass 2: acc += x @ Wr^T
    #pragma unroll 4
    for (int k = 0; k < 64; k += 4) {
        float4 a0 = *(const float4*)&sA[(i0 + 0) * AP + k];
        float4 a1 = *(const float4*)&sA[(i0 + 1) * AP + k];
        float4 a2 = *(const float4*)&sA[(i0 + 2) * AP + k];
        float4 a3 = *(const float4*)&sA[(i0 + 3) * AP + k];
        #pragma unroll
        for (int kk = 0; kk < 4; kk++) {
            ulonglong2 wp = *(const ulonglong2*)&sW[(k + kk) * WP + j0];
            float s0 = (kk == 0) ? a0.x : (kk == 1) ? a0.y : (kk == 2) ? a0.z : a0.w;
            float s1 = (kk == 0) ? a1.x : (kk == 1) ? a1.y : (kk == 2) ? a1.z : a1.w;
            float s2 = (kk == 0) ? a2.x : (kk == 1) ? a2.y : (kk == 2) ? a2.z : a2.w;
            float s3 = (kk == 0) ? a3.x : (kk == 1) ? a3.y : (kk == 2) ? a3.z : a3.w;
            unsigned long long p;
            p = bcast2(s0); fma2(accp[0][0], p, wp.x); fma2(accp[0][1], p, wp.y);
            p = bcast2(s1); fma2(accp[1][0], p, wp.x); fma2(accp[1][1], p, wp.y);
            p = bcast2(s2); fma2(accp[2][0], p, wp.x); fma2(accp[2][1], p, wp.y);
            p = bcast2(s3); fma2(accp[3][0], p, wp.x); fma2(accp[3][1], p, wp.y);
        }
    }

    // bias (packed) + unpack
    ulonglong2 bp = *(const ulonglong2*)&sB[j0];
    float acc[4][4];
    #pragma unroll
    for (int r = 0; r < 4; r++) {
        add2(accp[r][0], bp.x);
        add2(accp[r][1], bp.y);
        unpack2(accp[r][0], acc[r][0], acc[r][1]);
        unpack2(accp[r][1], acc[r][2], acc[r][3]);
    }

    if (mode == 0) {
        #pragma unroll
        for (int r = 0; r < 4; r++) {
            int node = node0 + i0 + r;
            if (node < n) {
                float4 st; float v;
                v = acc[r][0]; st.x = (v >= 0.f) ? v : 0.01f * v;
                v = acc[r][1]; st.y = (v >= 0.f) ? v : 0.01f * v;
                v = acc[r][2]; st.z = (v >= 0.f) ? v : 0.01f * v;
                v = acc[r][3]; st.w = (v >= 0.f) ? v : 0.01f * v;
                *(float4*)&out[(size_t)node * 64 + j0] = st;
            }
        }
    } else {
        // stage into sA, per-row L2 normalize
        __syncthreads();
        #pragma unroll
        for (int r = 0; r < 4; r++)
            *(float4*)&sA[(i0 + r) * AP + j0] =
                make_float4(acc[r][0], acc[r][1], acc[r][2], acc[r][3]);
        __syncthreads();
        #pragma unroll
        for (int it = 0; it < 8; it++) {
            int ni = wid + it * 8;
            int node = node0 + ni;
            if (node >= n) continue;
            float2 v = *(const float2*)&sA[ni * AP + 2 * lane];
            float ss = v.x * v.x + v.y * v.y;
            #pragma unroll
            for (int o = 16; o > 0; o >>= 1)
                ss += __shfl_xor_sync(full, ss, o);
            float s = 1.0f / fmaxf(sqrtf(ss), 1e-12f);
            *(float2*)&out[(size_t)node * 64 + 2 * lane] =
                make_float2(v.x * s, v.y * s);
        }
    }
}

// ================= launch (kernels ONLY — no host API calls) =================
extern "C" void kernel_launch(void* const* d_in, const int* in_sizes, int n_in,
                              void* d_out, int out_size)
{
    const float* x    = (const float*)d_in[0];
    const void*  edge = (const void*)d_in[1];
    // d_in[2] = edge_weight (ignored by SAGEConv)
    const float* W1l = (const float*)d_in[3];
    const float* b1  = (const float*)d_in[4];
    const float* W1r = (const float*)d_in[5];
    const float* W2l = (const float*)d_in[6];
    const float* b2  = (const float*)d_in[7];
    const float* W2r = (const float*)d_in[8];
    float* out = (float*)d_out;

    int n = in_sizes[0] / DD;
    int e = in_sizes[1] / 2;
    int nb = (n + SCAN_CHUNK - 1) / SCAN_CHUNK;

    convert_count_kernel<<<(e + 255) / 256, 256>>>(edge, e, n);
    scan_kernel<<<nb, SCAN_CHUNK>>>(n, e);
    fill_kernel<<<(e + 255) / 256, 256>>>(e);

    int nblocks = (n + NPB - 1) / NPB;
    layer_kernel<<<nblocks, 256>>>(x, W1l, b1, W1r, nullptr, n, 0); // -> g_h1
    layer_kernel<<<nblocks, 256>>>(x, W2l, b2, W2r, out,     n, 1); // g_h1 -> out
}

// round 17
// speedup vs baseline: 1.0299x; 1.0132x over previous
#include <cuda_runtime.h>

#define NMAX 50000
#define EMAX 800000
#define DD 64
#define NPB 64            // dst nodes per block
#define AP 64             // sA pitch (row-major [node][k])
#define WP 68             // sW pitch (transposed [k][j])
#define SCAN_CHUNK 1024
#define MAXB ((NMAX + SCAN_CHUNK - 1) / SCAN_CHUNK)   // 49
#define DSTMASK 0x1FFFF   // low 17 bits = dst id (n < 131072)

// -------- device scratch (no allocations allowed) --------
// g_deg is zero at module load and restored to zero by scan_kernel every
// invocation -> self-restoring invariant, no init kernel needed.
__device__ int   g_src[EMAX];
__device__ int   g_dst[EMAX];      // packed: (rank << 17) | dst
__device__ int   g_deg[NMAX];
__device__ int   g_rowptr[NMAX + 2];
__device__ int   g_col[EMAX];
__device__ int   g_bsum[MAXB + 1];
__device__ float g_h1[(size_t)NMAX * DD];

// ---- packed f32x2 helpers (sm_103a; ptxas never auto-emits FFMA2) ----
__device__ __forceinline__ unsigned long long bcast2(float a) {
    unsigned long long r;
    asm("mov.b64 %0, {%1, %1};" : "=l"(r) : "f"(a));
    return r;
}
__device__ __forceinline__ void fma2(unsigned long long& acc,
                                     unsigned long long a, unsigned long long b) {
    asm("fma.rn.f32x2 %0, %1, %2, %0;" : "+l"(acc) : "l"(a), "l"(b));
}
__device__ __forceinline__ void add2(unsigned long long& acc, unsigned long long b) {
    asm("add.rn.f32x2 %0, %0, %1;" : "+l"(acc) : "l"(b));
}
__device__ __forceinline__ void unpack2(unsigned long long p, float& lo, float& hi) {
    asm("mov.b64 {%0, %1}, %2;" : "=f"(lo), "=f"(hi) : "l"(p));
}

// ============ convert + count + inline dtype detection ============
__global__ void convert_count_kernel(const void* __restrict__ edge, int e, int n) {
    int t = threadIdx.x;
    int i = blockIdx.x * blockDim.x + t;
    const long long* p64 = (const long long*)edge;
    long long probe = 0;
    if (t < 64) probe = p64[t];
    int is64 = __syncthreads_and(t >= 64 || (probe >= 0 && probe < n));

    if (i >= e) return;
    int s, d;
    if (is64) {
        s = (int)p64[i];
        d = (int)p64[e + i];
    } else {
        const int* p = (const int*)edge;
        s = p[i];
        d = p[e + i];
    }
    s = min(max(s, 0), n - 1);
    d = min(max(d, 0), n - 1);
    g_src[i] = s;
    int r = atomicAdd(&g_deg[d], 1);
    g_dst[i] = d | (r << 17);
}

// ============ coalesced scan: bsum -> scan (block offsets inlined) ============
__global__ void bsum_kernel(int n) {
    __shared__ int ws[32];
    int b = blockIdx.x, t = threadIdx.x;
    int lane = t & 31, wid = t >> 5;
    int i = b * SCAN_CHUNK + t;
    int v = (i < n) ? g_deg[i] : 0;
    #pragma unroll
    for (int o = 16; o > 0; o >>= 1) v += __shfl_xor_sync(0xffffffffu, v, o);
    if (lane == 0) ws[wid] = v;
    __syncthreads();
    if (t < 32) {
        int s = ws[t];
        #pragma unroll
        for (int o = 16; o > 0; o >>= 1) s += __shfl_xor_sync(0xffffffffu, s, o);
        if (t == 0) g_bsum[b] = s;
    }
}

// per-chunk exclusive scan; block offset computed in-kernel from g_bsum.
// Also restores g_deg[i] = 0 after consumption (invariant for next replay).
__global__ void scan_kernel(int n, int e) {
    __shared__ int ws[32];
    __shared__ int sOff;
    int b = blockIdx.x, t = threadIdx.x;
    int lane = t & 31, wid = t >> 5;

    if (wid == 0) {
        int off = 0;
        for (int j = lane; j < b; j += 32) off += g_bsum[j];
        #pragma unroll
        for (int o = 16; o > 0; o >>= 1) off += __shfl_xor_sync(0xffffffffu, off, o);
        if (lane == 0) sOff = off;
    }

    int i = b * SCAN_CHUNK + t;
    int v = (i < n) ? g_deg[i] : 0;
    int x = v;
    #pragma unroll
    for (int o = 1; o < 32; o <<= 1) {
        int y = __shfl_up_sync(0xffffffffu, x, o);
        if (lane >= o) x += y;
    }
    if (lane == 31) ws[wid] = x;
    __syncthreads();
    if (wid == 0) {
        int w = ws[lane];
        #pragma unroll
        for (int o = 1; o < 32; o <<= 1) {
            int y = __shfl_up_sync(0xffffffffu, w, o);
            if (lane >= o) w += y;
        }
        ws[lane] = w;
    }
    __syncthreads();
    int incl = x + (wid > 0 ? ws[wid - 1] : 0);
    int excl = incl - v + sOff;
    if (i < n) {
        g_rowptr[i] = excl;
        g_deg[i] = 0;            // restore invariant for next invocation
    }
    if (b == 0 && t == 0) g_rowptr[n] = e;
}

// atomic-free fill: slot = rowptr[dst] + rank (rank packed in g_dst)
__global__ void fill_kernel(int e) {
    int i = blockIdx.x * blockDim.x + threadIdx.x;
    if (i < e) {
        int v = g_dst[i];
        int d = v & DSTMASK;
        int r = v >> 17;
        g_col[g_rowptr[d] + r] = g_src[i];
    }
}

// ================= fused layer (127.5us structure + reg cap for occupancy) ====
// mode 0: in = x param, out = g_h1, epilogue leaky_relu(0.01)
// mode 1: in = g_h1,    out = out param, epilogue row-L2-normalize
__global__ __launch_bounds__(256, 4) void layer_kernel(
    const float* __restrict__ in_p,
    const float* __restrict__ Wl,      // [64,64] row-major
    const float* __restrict__ bias,    // [64]
    const float* __restrict__ Wr,      // [64,64] row-major
    float* __restrict__ out_p,
    int n, int mode)
{
    __shared__ float sA[NPB * AP];     // [64 nodes][64 k] row-major
    __shared__ float sW[64 * WP];      // [64 k][64 j] transposed weight
    __shared__ float sB[64];

    const float* __restrict__ in = (mode == 0) ? in_p : g_h1;
    float* __restrict__ out      = (mode == 0) ? g_h1 : out_p;

    const unsigned full = 0xffffffffu;
    int t = threadIdx.x;
    int wid = t >> 5, lane = t & 31;
    int half = lane >> 4;        // 0/1: which edge of the pair
    int c4 = (lane & 15) * 4;    // float4 column group
    int node0 = blockIdx.x * NPB;

    // load Wl^T and bias
    for (int idx = t; idx < 64 * 64; idx += 256) {
        int j = idx >> 6, k = idx & 63;
        sW[k * WP + j] = Wl[idx];
    }
    if (t < 64) sB[t] = bias[t];

    // ---- prefetch rowptr for this warp's 8 nodes (lanes 0..15) ----
    int pidx;
    if (lane < 8)       pidx = node0 + wid + lane * 8;
    else if (lane < 16) pidx = node0 + wid + (lane - 8) * 8 + 1;
    else                pidx = n;
    pidx = min(pidx, n);
    int rp = g_rowptr[pidx];

    // ---- prefetch self rows x[node] for all 8 nodes ----
    float2 xs[8];
    #pragma unroll
    for (int it = 0; it < 8; it++) {
        int node = min(node0 + wid + it * 8, n - 1);
        xs[it] = *(const float2*)&in[(size_t)node * 64 + 2 * lane];
    }

    // ---- phase 1: mean aggregation -> sA ----
    #pragma unroll
    for (int it = 0; it < 8; it++) {
        int ni = wid + it * 8;
        int node = node0 + ni;
        float4 a0 = {0.f, 0.f, 0.f, 0.f}, a1 = {0.f, 0.f, 0.f, 0.f};
        int beg = __shfl_sync(full, rp, it);
        int end = __shfl_sync(full, rp, it + 8);
        if (node < n) {
            int e0 = beg;
            for (; e0 + 4 <= end; e0 += 4) {
                int sa = g_col[e0 + half];
                int sb = g_col[e0 + 2 + half];
                float4 v0 = *(const float4*)&in[(size_t)sa * 64 + c4];
                float4 v1 = *(const float4*)&in[(size_t)sb * 64 + c4];
                a0.x += v0.x; a0.y += v0.y; a0.z += v0.z; a0.w += v0.w;
                a1.x += v1.x; a1.y += v1.y; a1.z += v1.z; a1.w += v1.w;
            }
            if (e0 + 2 <= end) {
                int sa = g_col[e0 + half];
                float4 v0 = *(const float4*)&in[(size_t)sa * 64 + c4];
                a0.x += v0.x; a0.y += v0.y; a0.z += v0.z; a0.w += v0.w;
                e0 += 2;
            }
            if (e0 < end && half == 0) {
                int sa = g_col[e0];
                float4 v0 = *(const float4*)&in[(size_t)sa * 64 + c4];
                a1.x += v0.x; a1.y += v0.y; a1.z += v0.z; a1.w += v0.w;
            }
            a0.x += a1.x; a0.y += a1.y; a0.z += a1.z; a0.w += a1.w;
            a0.x += __shfl_xor_sync(full, a0.x, 16);
            a0.y += __shfl_xor_sync(full, a0.y, 16);
            a0.z += __shfl_xor_sync(full, a0.z, 16);
            a0.w += __shfl_xor_sync(full, a0.w, 16);
            int deg = end - beg;
            float inv = 1.0f / (float)(deg > 0 ? deg : 1);
            a0.x *= inv; a0.y *= inv; a0.z *= inv; a0.w *= inv;
        }
        if (half == 0)
            *(float4*)&sA[ni * AP + c4] = a0;
    }
    __syncthreads();

    // ---- GEMM with packed f32x2 accumulators (4x4 tile) ----
    int rg = t >> 4, cg = t & 15;
    int i0 = rg * 4, j0 = cg * 4;
    unsigned long long accp[4][2] = {};

    // pass 1: acc += mean @ Wl^T
    #pragma unroll 4
    for (int k = 0; k < 64; k += 4) {
        float4 a0 = *(const float4*)&sA[(i0 + 0) * AP + k];
        float4 a1 = *(const float4*)&sA[(i0 + 1) * AP + k];
        float4 a2 = *(const float4*)&sA[(i0 + 2) * AP + k];
        float4 a3 = *(const float4*)&sA[(i0 + 3) * AP + k];
        #pragma unroll
        for (int kk = 0; kk < 4; kk++) {
            ulonglong2 wp = *(const ulonglong2*)&sW[(k + kk) * WP + j0];
            float s0 = (kk == 0) ? a0.x : (kk == 1) ? a0.y : (kk == 2) ? a0.z : a0.w;
            float s1 = (kk == 0) ? a1.x : (kk == 1) ? a1.y : (kk == 2) ? a1.z : a1.w;
            float s2 = (kk == 0) ? a2.x : (kk == 1) ? a2.y : (kk == 2) ? a2.z : a2.w;
            float s3 = (kk == 0) ? a3.x : (kk == 1) ? a3.y : (kk == 2) ? a3.z : a3.w;
            unsigned long long p;
            p = bcast2(s0); fma2(accp[0][0], p, wp.x); fma2(accp[0][1], p, wp.y);
            p = bcast2(s1); fma2(accp[1][0], p, wp.x); fma2(accp[1][1], p, wp.y);
            p = bcast2(s2); fma2(accp[2][0], p, wp.x); fma2(accp[2][1], p, wp.y);
            p = bcast2(s3); fma2(accp[3][0], p, wp.x); fma2(accp[3][1], p, wp.y);
        }
    }
    __syncthreads();

    // swap operands: sA <- x, sW <- Wr^T
    #pragma unroll
    for (int it = 0; it < 8; it++) {
        int ni = wid + it * 8;
        *(float2*)&sA[ni * AP + 2 * lane] = xs[it];
    }
    for (int idx = t; idx < 64 * 64; idx += 256) {
        int j = idx >> 6, k = idx & 63;
        sW[k * WP + j] = Wr[idx];
    }
    __syncthreads();

    // pass 2: acc += x @ Wr^T
    #pragma unroll 4
    for (int k = 0; k < 64; k += 4) {
        float4 a0 = *(const float4*)&sA[(i0 + 0) * AP + k];
        float4 a1 = *(const float4*)&sA[(i0 + 1) * AP + k];
        float4 a2 = *(const float4*)&sA[(i0 + 2) * AP + k];
        float4 a3 = *(const float4*)&sA[(i0 + 3) * AP + k];
        #pragma unroll
        for (int kk = 0; kk < 4; kk++) {
            ulonglong2 wp = *(const ulonglong2*)&sW[(k + kk) * WP + j0];
            float s0 = (kk == 0) ? a0.x : (kk == 1) ? a0.y : (kk == 2) ? a0.z : a0.w;
            float s1 = (kk == 0) ? a1.x : (kk == 1) ? a1.y : (kk == 2) ? a1.z : a1.w;
            float s2 = (kk == 0) ? a2.x : (kk == 1) ? a2.y : (kk == 2) ? a2.z : a2.w;
            float s3 = (kk == 0) ? a3.x : (kk == 1) ? a3.y : (kk == 2) ? a3.z : a3.w;
            unsigned long long p;
            p = bcast2(s0); fma2(accp[0][0], p, wp.x); fma2(accp[0][1], p, wp.y);
            p = bcast2(s1); fma2(accp[1][0], p, wp.x); fma2(accp[1][1], p, wp.y);
            p = bcast2(s2); fma2(accp[2][0], p, wp.x); fma2(accp[2][1], p, wp.y);
            p = bcast2(s3); fma2(accp[3][0], p, wp.x); fma2(accp[3][1], p, wp.y);
        }
    }

    // bias (packed) + unpack
    ulonglong2 bp = *(const ulonglong2*)&sB[j0];
    float acc[4][4];
    #pragma unroll
    for (int r = 0; r < 4; r++) {
        add2(accp[r][0], bp.x);
        add2(accp[r][1], bp.y);
        unpack2(accp[r][0], acc[r][0], acc[r][1]);
        unpack2(accp[r][1], acc[r][2], acc[r][3]);
    }

    if (mode == 0) {
        #pragma unroll
        for (int r = 0; r < 4; r++) {
            int node = node0 + i0 + r;
            if (node < n) {
                float4 st; float v;
                v = acc[r][0]; st.x = (v >= 0.f) ? v : 0.01f * v;
                v = acc[r][1]; st.y = (v >= 0.f) ? v : 0.01f * v;
                v = acc[r][2]; st.z = (v >= 0.f) ? v : 0.01f * v;
                v = acc[r][3]; st.w = (v >= 0.f) ? v : 0.01f * v;
                *(float4*)&out[(size_t)node * 64 + j0] = st;
            }
        }
    } else {
        // stage into sA, per-row L2 normalize
        __syncthreads();
        #pragma unroll
        for (int r = 0; r < 4; r++)
            *(float4*)&sA[(i0 + r) * AP + j0] =
                make_float4(acc[r][0], acc[r][1], acc[r][2], acc[r][3]);
        __syncthreads();
        #pragma unroll
        for (int it = 0; it < 8; it++) {
            int ni = wid + it * 8;
            int node = node0 + ni;
            if (node >= n) continue;
            float2 v = *(const float2*)&sA[ni * AP + 2 * lane];
            float ss = v.x * v.x + v.y * v.y;
            #pragma unroll
            for (int o = 16; o > 0; o >>= 1)
                ss += __shfl_xor_sync(full, ss, o);
            float s = 1.0f / fmaxf(sqrtf(ss), 1e-12f);
            *(float2*)&out[(size_t)node * 64 + 2 * lane] =
                make_float2(v.x * s, v.y * s);
        }
    }
}

// ================= launch (kernels ONLY — no host API calls) =================
extern "C" void kernel_launch(void* const* d_in, const int* in_sizes, int n_in,
                              void* d_out, int out_size)
{
    const float* x    = (const float*)d_in[0];
    const void*  edge = (const void*)d_in[1];
    // d_in[2] = edge_weight (ignored by SAGEConv)
    const float* W1l = (const float*)d_in[3];
    const float* b1  = (const float*)d_in[4];
    const float* W1r = (const float*)d_in[5];
    const float* W2l = (const float*)d_in[6];
    const float* b2  = (const float*)d_in[7];
    const float* W2r = (const float*)d_in[8];
    float* out = (float*)d_out;

    int n = in_sizes[0] / DD;
    int e = in_sizes[1] / 2;
    int nb = (n + SCAN_CHUNK - 1) / SCAN_CHUNK;

    convert_count_kernel<<<(e + 255) / 256, 256>>>(edge, e, n);
    bsum_kernel<<<nb, SCAN_CHUNK>>>(n);
    scan_kernel<<<nb, SCAN_CHUNK>>>(n, e);
    fill_kernel<<<(e + 255) / 256, 256>>>(e);

    int nblocks = (n + NPB - 1) / NPB;
    layer_kernel<<<nblocks, 256>>>(x, W1l, b1, W1r, nullptr, n, 0); // -> g_h1
    layer_kernel<<<nblocks, 256>>>(x, W2l, b2, W2r, out,     n, 1); // g_h1 -> out
}